// round 4
// baseline (speedup 1.0000x reference)
#include <cuda_runtime.h>

#define B 16
#define S 4096
#define H 1024
#define JCHUNK 128

// ---- device scratch (no allocations allowed) ----
__device__ float g_scores[B * S];
__device__ float g_m[B];
__device__ float g_l[B];
__device__ int   g_start[B];
__device__ int   g_qlen[B];
__device__ int   g_maxlen;

// K0: decode query_indices, compute per-batch start/qlen and global max_len.
// Handles BOTH int32 and int64 storage: if the buffer is int64 (little-endian,
// values < 2^31), every odd 32-bit word is the zero high-half.
__global__ void k0_setup(const int* __restrict__ qi32) {
    if (threadIdx.x == 0) {
        bool is64 = true;
        for (int i = 1; i < 32; i += 2) {
            if (qi32[i] != 0) { is64 = false; break; }
        }
        int maxlen = 0;
        for (int b = 0; b < B; b++) {
            int s, e;
            if (is64) { s = qi32[4 * b];  e = qi32[4 * b + 2]; }
            else      { s = qi32[2 * b];  e = qi32[2 * b + 1]; }
            g_start[b] = s;
            g_qlen[b]  = e - s;
            int ml = e + 1 - s;
            if (ml > maxlen) maxlen = ml;
        }
        g_maxlen = maxlen;
    }
}

// K1: scores[b, j] = am[b] * dot(hs[b, start+j, :], w)  for j < qlen
//     scores[b, j] = 0                                   for qlen <= j < max_len
// One warp per row, 8 rows per 256-thread block. w staged in smem.
__global__ void k1_scores(const float* __restrict__ hs,
                          const float* __restrict__ am,
                          const float* __restrict__ w) {
    __shared__ float sw[H];
    const int b = blockIdx.y;
    const int jbase = blockIdx.x * 8;
    const int maxlen = g_maxlen;
    if (jbase >= maxlen) return;

    for (int i = threadIdx.x; i < H; i += blockDim.x) sw[i] = w[i];
    __syncthreads();

    const int warp = threadIdx.x >> 5;
    const int lane = threadIdx.x & 31;
    const int j = jbase + warp;
    if (j >= maxlen) return;

    const int qlen = g_qlen[b];
    float sc = 0.0f;
    if (j < qlen) {
        const float* x = hs + ((size_t)(b * S + g_start[b] + j)) * H;
        float acc = 0.0f;
#pragma unroll
        for (int it = 0; it < 8; it++) {
            const int idx = (lane + it * 32) * 4;
            float4 xv = *reinterpret_cast<const float4*>(x + idx);
            float4 wv = *reinterpret_cast<const float4*>(sw + idx);
            acc += xv.x * wv.x + xv.y * wv.y + xv.z * wv.z + xv.w * wv.w;
        }
#pragma unroll
        for (int o = 16; o; o >>= 1) acc += __shfl_xor_sync(0xffffffffu, acc, o);
        sc = am[b] * acc;
    }
    if (lane == 0) g_scores[b * S + j] = sc;
}

// K2: per-batch softmax statistics (max, sum of exp) over [0, max_len); zero d_out.
__global__ void k2_softmax(float* __restrict__ out) {
    const int b = blockIdx.x;
    const int maxlen = g_maxlen;
    const int tid = threadIdx.x;
    __shared__ float red[256];

    float m = -1e30f;
    for (int j = tid; j < maxlen; j += 256) m = fmaxf(m, g_scores[b * S + j]);
    red[tid] = m;
    __syncthreads();
    for (int o = 128; o; o >>= 1) {
        if (tid < o) red[tid] = fmaxf(red[tid], red[tid + o]);
        __syncthreads();
    }
    m = red[0];
    __syncthreads();

    float l = 0.0f;
    for (int j = tid; j < maxlen; j += 256) l += expf(g_scores[b * S + j] - m);
    red[tid] = l;
    __syncthreads();
    for (int o = 128; o; o >>= 1) {
        if (tid < o) red[tid] += red[tid + o];
        __syncthreads();
    }

    if (tid == 0) {
        g_m[b] = m;
        g_l[b] = red[0];
    }
    // zero-init output rows for this batch (d_out is poisoned by the harness)
    for (int h = tid; h < H; h += 256) out[b * H + h] = 0.0f;
}

// K3: out[b, h] += sum_{j in chunk} p[j] * am[b] * hs[b, start+j, h]
// grid = (S/JCHUNK, H/256, B); probabilities staged in smem; coalesced columns.
__global__ void k3_agg(const float* __restrict__ hs,
                       const float* __restrict__ am,
                       float* __restrict__ out) {
    const int b = blockIdx.z;
    const int qlen = g_qlen[b];
    const int jbase = blockIdx.x * JCHUNK;
    if (jbase >= qlen) return;

    const int nj = min(JCHUNK, qlen - jbase);
    __shared__ float p[JCHUNK];

    const float m = g_m[b];
    const float inv_l = 1.0f / g_l[b];
    const float amb = am[b];
    for (int jj = threadIdx.x; jj < nj; jj += 256)
        p[jj] = expf(g_scores[b * S + jbase + jj] - m) * inv_l * amb;
    __syncthreads();

    const int h = blockIdx.y * 256 + threadIdx.x;
    const float* x = hs + ((size_t)(b * S + g_start[b] + jbase)) * H + h;

    float acc = 0.0f;
#pragma unroll 8
    for (int jj = 0; jj < nj; jj++) acc += p[jj] * x[(size_t)jj * H];

    atomicAdd(&out[b * H + h], acc);
}

extern "C" void kernel_launch(void* const* d_in, const int* in_sizes, int n_in,
                              void* d_out, int out_size) {
    // Identify inputs by element count (robust to metadata ordering):
    //   hidden_states: B*S*H = 67108864 (f32)
    //   query_indices: 2*B   = 32       (i32 or i64 — detected in k0)
    //   attention_mask: B    = 16       (f32)
    //   w:             H     = 1024     (f32)
    const float* hs = nullptr;
    const int*   qi = nullptr;
    const float* am = nullptr;
    const float* w  = nullptr;
    for (int i = 0; i < n_in; i++) {
        switch (in_sizes[i]) {
            case B * S * H: hs = (const float*)d_in[i]; break;
            case 2 * B:     qi = (const int*)d_in[i];   break;
            case B:         am = (const float*)d_in[i]; break;
            case H:         w  = (const float*)d_in[i]; break;
        }
    }
    float* out = (float*)d_out;

    k0_setup<<<1, 32>>>(qi);

    dim3 g1(S / 8, B);
    k1_scores<<<g1, 256>>>(hs, am, w);

    k2_softmax<<<B, 256>>>(out);

    dim3 g3((S + JCHUNK - 1) / JCHUNK, H / 256, B);
    k3_agg<<<g3, 256>>>(hs, am, out);
}